// round 16
// baseline (speedup 1.0000x reference)
#include <cuda_runtime.h>
#include <cuda_bf16.h>
#include <math.h>
#include <cstdint>

// ---------------------------------------------------------------------------
// Problem constants
// ---------------------------------------------------------------------------
#define BATCH   512
#define N_IN    128
#define N_OUT   256
#define NBASIS  6
#define NFEAT   7
#define KDIM    (N_IN*NFEAT)          // 896

#define OUT_ELEMS (BATCH * N_OUT)     // 131072

// GEMM tiling (R9/R13/R15-proven)
#define BM 64
#define BN 64
#define BK 64
#define KSPLIT (KDIM / BK)             // 14
#define MT (BATCH / BM)                // 8
#define NT (N_OUT / BN)                // 4

#define NI 10                          // distinct i per 64-wide k-slice
#define NEVAL (BM * NI)                // 640 evals per operand per CTA
#define LDS 72                         // padded SMEM stride (bf16 units)

// ---------------------------------------------------------------------------
// Device globals (no allocation allowed)
// ---------------------------------------------------------------------------
__device__ float g_P[KSPLIT * OUT_ELEMS];   // split-K partials (7.3 MB)

// ---------------------------------------------------------------------------
// warp-MMA helpers (sm_80+ PTX, compiles at compute_103)
// ---------------------------------------------------------------------------
__device__ __forceinline__ uint32_t smem_u32(const void* p) {
    uint32_t a;
    asm("{ .reg .u64 t; cvta.to.shared.u64 t, %1; cvt.u32.u64 %0, t; }"
        : "=r"(a) : "l"(p));
    return a;
}
__device__ __forceinline__ void ldmx4(uint32_t* r, uint32_t addr) {
    asm volatile("ldmatrix.sync.aligned.m8n8.x4.shared.b16 {%0,%1,%2,%3}, [%4];"
                 : "=r"(r[0]), "=r"(r[1]), "=r"(r[2]), "=r"(r[3]) : "r"(addr));
}
__device__ __forceinline__ void mma16816(float* c, const uint32_t* a, const uint32_t* b) {
    asm volatile(
        "mma.sync.aligned.m16n8k16.row.col.f32.bf16.bf16.f32 "
        "{%0,%1,%2,%3}, {%4,%5,%6,%7}, {%8,%9}, {%0,%1,%2,%3};"
        : "+f"(c[0]), "+f"(c[1]), "+f"(c[2]), "+f"(c[3])
        : "r"(a[0]), "r"(a[1]), "r"(a[2]), "r"(a[3]), "r"(b[0]), "r"(b[1]));
}

// bf16 hi/lo split
__device__ __forceinline__ void split2(float v, __nv_bfloat16& hi, __nv_bfloat16& lo) {
    hi = __float2bfloat16(v);
    lo = __float2bfloat16(v - __bfloat162float(hi));
}

// ---------------------------------------------------------------------------
// Kernel 1: fused build + HMMA, writes split-K partials. (unchanged, R15)
// ---------------------------------------------------------------------------
__global__ void __launch_bounds__(256, 4)
kan_kernel(const float* __restrict__ x,
           const float* __restrict__ grid,
           const float* __restrict__ c_basis,
           const float* __restrict__ c_spl,
           const float* __restrict__ c_res) {
    __shared__ __nv_bfloat16 sAhi[BM * LDS];
    __shared__ __nv_bfloat16 sAlo[BM * LDS];
    __shared__ __nv_bfloat16 sBhi[BN * LDS];
    __shared__ __nv_bfloat16 sBlo[BN * LDS];

    const int tid = threadIdx.x;
    const int wid = tid >> 5;
    const int lane = tid & 31;

    const int m0 = blockIdx.x * BM;
    const int n0 = blockIdx.y * BN;
    const int z  = blockIdx.z;
    const int k0 = z * BK;
    const int i_lo = k0 / NFEAT;

    // ---- LOAD PHASE: issue every global read up front (MLP ~18) ----
    const float gk0 = grid[0];
    const float gk1 = grid[1];

    float  xv[3];
    float  cs[3], cr[3];
    float2 cb0[3], cb1[3], cb2[3];
    #pragma unroll
    for (int t = 0; t < 3; t++) {
        int p  = tid + t * 256;
        int pc = p < NEVAL ? p : NEVAL - 1;       // clamp for safe addresses
        int row = pc / NI;
        int i   = i_lo + (pc - row * NI);
        xv[t] = x[(m0 + row) * N_IN + i];
        int j = (n0 + row) * N_IN + i;
        cs[t] = c_spl[j];
        cr[t] = c_res[j];
        const float2* cb = (const float2*)(c_basis + (long)j * NBASIS);
        cb0[t] = cb[0]; cb1[t] = cb[1]; cb2[t] = cb[2];
    }

    // ---- zero A tiles while loads are in flight (pure STS) ----
    {
        float4 zz = make_float4(0.f, 0.f, 0.f, 0.f);
        float4* a0 = (float4*)sAhi;
        float4* a1 = (float4*)sAlo;
        #pragma unroll
        for (int t = 0; t < 3; t++) {
            int p = tid + t * 256;
            if (p < (BM * LDS) / 8) { a0[p] = zz; a1[p] = zz; }
        }
    }
    __syncthreads();

    const float rinv = 1.0f / (gk1 - gk0);

    // ---- COMPUTE A: closed-form cubic B-spline + swish ----
    #pragma unroll
    for (int t = 0; t < 3; t++) {
        int p = tid + t * 256;
        if (p < NEVAL) {
            const int row = p / NI;
            const int kb  = (i_lo + (p - row * NI)) * NFEAT - k0;
            const float xvv = xv[t];

            float ft = (xvv - gk0) * rinv;
            if (ft >= 0.0f && ft < 9.0f) {
                int j = (int)ft;
                float u  = ft - (float)j;
                float um = 1.0f - u;
                float u2 = u * u, u3 = u2 * u;
                float v[4];
                v[0] = (1.0f / 6.0f) * um * um * um;
                v[1] = 0.5f * u3 - u2 + (2.0f / 3.0f);
                v[2] = -0.5f * u3 + 0.5f * u2 + 0.5f * u + (1.0f / 6.0f);
                v[3] = (1.0f / 6.0f) * u3;
                #pragma unroll
                for (int s = 0; s < 4; s++) {
                    int m = j - 3 + s;
                    int k = kb + m;
                    if ((unsigned)m < NBASIS && (unsigned)k < BK) {
                        __nv_bfloat16 hi, lo;
                        split2(v[s], hi, lo);
                        sAhi[row * LDS + k] = hi;
                        sAlo[row * LDS + k] = lo;
                    }
                }
            }
            int k = kb + NBASIS;
            if ((unsigned)k < BK) {
                float sw = xvv / (1.0f + __expf(-xvv));
                __nv_bfloat16 hi, lo;
                split2(sw, hi, lo);
                sAhi[row * LDS + k] = hi;
                sAlo[row * LDS + k] = lo;
            }
        }
    }

    // ---- COMPUTE B: scaled weights, from registers ----
    #pragma unroll
    for (int t = 0; t < 3; t++) {
        int p = tid + t * 256;
        if (p < NEVAL) {
            const int row = p / NI;
            const int kb  = (i_lo + (p - row * NI)) * NFEAT - k0;
            float csv = cs[t] * (1.0f / N_IN);
            float crv = cr[t] * (1.0f / N_IN);
            float w[NFEAT];
            w[0] = csv * cb0[t].x; w[1] = csv * cb0[t].y;
            w[2] = csv * cb1[t].x; w[3] = csv * cb1[t].y;
            w[4] = csv * cb2[t].x; w[5] = csv * cb2[t].y;
            w[6] = crv;
            #pragma unroll
            for (int m = 0; m < NFEAT; m++) {
                int k = kb + m;
                if ((unsigned)k < BK) {
                    __nv_bfloat16 hi, lo;
                    split2(w[m], hi, lo);
                    sBhi[row * LDS + k] = hi;
                    sBlo[row * LDS + k] = lo;
                }
            }
        }
    }
    __syncthreads();

    // ---- MMA: 8 warps, 4(m) x 2(n); warp tile 16 x 32 ----
    const int wm = wid & 3;
    const int wn = wid >> 2;

    float acc[4][4] = {};

    const uint32_t aHiBase = smem_u32(sAhi);
    const uint32_t aLoBase = smem_u32(sAlo);
    const uint32_t bHiBase = smem_u32(sBhi);
    const uint32_t bLoBase = smem_u32(sBlo);

    const int ar = wm * 16 + (lane & 15);
    const uint32_t aOff = (uint32_t)(ar * LDS) * 2 + (uint32_t)(lane >> 4) * 16;
    const int br4 = wn * 32 + ((lane >> 4) & 1) * 8 + (lane & 7);
    const uint32_t bOff4 = (uint32_t)(br4 * LDS) * 2 + (uint32_t)((lane >> 3) & 1) * 16;

    #pragma unroll
    for (int ks = 0; ks < 4; ks++) {
        const uint32_t kByte = (uint32_t)(ks * 16) * 2;

        uint32_t aHi[4], aLo[4];
        ldmx4(aHi, aHiBase + aOff + kByte);
        ldmx4(aLo, aLoBase + aOff + kByte);

        #pragma unroll
        for (int ntp = 0; ntp < 2; ntp++) {
            const uint32_t bo = bOff4 + (uint32_t)(ntp * 16 * LDS) * 2 + kByte;
            uint32_t bHi[4], bLo[4];
            ldmx4(bHi, bHiBase + bo);
            ldmx4(bLo, bLoBase + bo);
            mma16816(acc[2 * ntp],     aHi, bHi);
            mma16816(acc[2 * ntp],     aHi, bLo);
            mma16816(acc[2 * ntp],     aLo, bHi);
            mma16816(acc[2 * ntp + 1], aHi, bHi + 2);
            mma16816(acc[2 * ntp + 1], aHi, bLo + 2);
            mma16816(acc[2 * ntp + 1], aLo, bHi + 2);
        }
    }

    // ---- store split-K partials (plain STG); kernel boundary = sync ----
    {
        const int g = lane >> 2, t4 = lane & 3;
        const int r0 = m0 + wm * 16 + g;
        float* base0 = &g_P[(long)z * OUT_ELEMS + (long)r0 * N_OUT + n0 + wn * 32];
        float* base1 = base0 + 8 * N_OUT;
        #pragma unroll
        for (int nt = 0; nt < 4; nt++) {
            int cc = nt * 8 + 2 * t4;
            *(float2*)(base0 + cc) = make_float2(acc[nt][0], acc[nt][1]);
            *(float2*)(base1 + cc) = make_float2(acc[nt][2], acc[nt][3]);
        }
    }
}

// ---------------------------------------------------------------------------
// Kernel 2: chip-wide split-K reduction, scalar loads for max warp count.
// 512 CTAs x 256 threads; one float output per thread; 14 coalesced LDG.32
// (each warp load = exactly one 128B line), MLP = 14.
// ---------------------------------------------------------------------------
__global__ void __launch_bounds__(256)
reduce_kernel(float* __restrict__ out) {
    const int e = blockIdx.x * 256 + threadIdx.x;   // [0, 131072) float index
    const float* p = g_P + e;
    float v[KSPLIT];
    #pragma unroll
    for (int s = 0; s < KSPLIT; s++) v[s] = p[s * OUT_ELEMS];
    float sum = 0.0f;
    #pragma unroll
    for (int s = 0; s < KSPLIT; s++) sum += v[s];
    out[e] = sum;
}

// ---------------------------------------------------------------------------
// Launch: two kernels (boundary replaces the handshake)
// ---------------------------------------------------------------------------
extern "C" void kernel_launch(void* const* d_in, const int* in_sizes, int n_in,
                              void* d_out, int out_size) {
    const float* x       = (const float*)d_in[0];   // (512,128)
    const float* grid    = (const float*)d_in[1];   // (32768,10), rows identical
    const float* c_basis = (const float*)d_in[2];   // (32768,6)
    const float* c_spl   = (const float*)d_in[3];   // (32768,)
    const float* c_res   = (const float*)d_in[4];   // (32768,)
    float* out = (float*)d_out;                     // (512,256)

    dim3 gdim(MT, NT, KSPLIT);   // 8 x 4 x 14 = 448 CTAs
    kan_kernel<<<gdim, 256>>>(x, grid, c_basis, c_spl, c_res);
    reduce_kernel<<<OUT_ELEMS / 256, 256>>>(out);   // 512 CTAs
}